// round 6
// baseline (speedup 1.0000x reference)
#include <cuda_runtime.h>
#include <cuda_bf16.h>
#include <cstdint>
#include <math.h>

// Problem constants
#define B_DIM 8
#define C_DIM 256
#define S_DIM 8192            // D*H*W
#define N_PTS 65536           // B*S
#define N_CODES 1024
#define Z_ELEMS 16777216
#define BATCH_STRIDE 2097152  // C*S

// Output layout (concatenated, fp32)
#define ZQ_OFF 0
#define IDX_OFF 16777216
#define LOSS_OFF 16842752
#define PERP_OFF 16842753

// Phase-1 GEMM tiling: block = 128 pts x 128 codes x 256 k (all-K resident)
#define ZT_STRIDE 136         // 128 m + 8 pad (bf16)
#define ET_STRIDE 264         // 256 k + 8 pad (bf16)
#define SMEM_GEMM (256*ZT_STRIDE*2 + 128*ET_STRIDE*2)   // 137216 B
#define SMEM_TILE64 (256*64*4)                           // 65536 B

// Scratch (device globals)
__device__ float          g_e2[N_CODES];          // ||e_j||^2 (R4 shuffle chain)
__device__ float          g_A[N_PTS];             // sum z^2 (sequential chain)
__device__ float          g_U[N_PTS];             // sum |z| (for error bound)
__device__ int            g_idx[N_PTS];
__device__ float          g_cnt[N_CODES];
__device__ double         g_loss;
__device__ unsigned short g_zbf[Z_ELEMS];         // z as bf16, same [b][k][s] layout
__device__ unsigned short g_ebf[N_CODES * C_DIM]; // embed as bf16 [code][k]
__device__ int2           g_slots[N_PTS * 128];   // per (pt,seg,lanepair): top-2 {v_bits, j}

// ---- PTX helpers -----------------------------------------------------------
__device__ __forceinline__ void ldsm4(unsigned a, unsigned& r0, unsigned& r1,
                                      unsigned& r2, unsigned& r3) {
    asm volatile("ldmatrix.sync.aligned.m8n8.x4.shared.b16 {%0,%1,%2,%3}, [%4];"
                 : "=r"(r0), "=r"(r1), "=r"(r2), "=r"(r3) : "r"(a));
}
__device__ __forceinline__ void ldsm4t(unsigned a, unsigned& r0, unsigned& r1,
                                       unsigned& r2, unsigned& r3) {
    asm volatile("ldmatrix.sync.aligned.m8n8.x4.trans.shared.b16 {%0,%1,%2,%3}, [%4];"
                 : "=r"(r0), "=r"(r1), "=r"(r2), "=r"(r3) : "r"(a));
}
__device__ __forceinline__ void mma_bf16(float* d, const unsigned* a, const unsigned* b) {
    asm volatile(
        "mma.sync.aligned.m16n8k16.row.col.f32.bf16.bf16.f32 "
        "{%0,%1,%2,%3}, {%4,%5,%6,%7}, {%8,%9}, {%0,%1,%2,%3};"
        : "+f"(d[0]), "+f"(d[1]), "+f"(d[2]), "+f"(d[3])
        : "r"(a[0]), "r"(a[1]), "r"(a[2]), "r"(a[3]), "r"(b[0]), "r"(b[1]));
}

// ---------------------------------------------------------------------------
// K1: ||e_j||^2 (unchanged R4 chain), embed->bf16, zero accumulators.
// grid 128 x 256.
// ---------------------------------------------------------------------------
__global__ void vq_prep_e(const float* __restrict__ embed) {
    int t = threadIdx.x, lane = t & 31;
    int code = blockIdx.x * 8 + (t >> 5);
    const float* row = embed + code * C_DIM;
    float s = 0.f;
#pragma unroll
    for (int q = 0; q < 8; ++q) { float e = row[lane + q * 32]; s = fmaf(e, e, s); }
#pragma unroll
    for (int off = 16; off > 0; off >>= 1) s += __shfl_down_sync(0xffffffffu, s, off);
    if (lane == 0) g_e2[code] = s;

    // bf16 copy of embed: this block handles 8 codes = 2048 elems
#pragma unroll
    for (int i = 0; i < 8; ++i) {
        int gi = blockIdx.x * 2048 + i * 256 + t;
        g_ebf[gi] = __bfloat16_as_ushort(__float2bfloat16_rn(embed[gi]));
    }
    if (blockIdx.x == 0) {
        for (int i = t; i < N_CODES; i += 256) g_cnt[i] = 0.f;
        if (t == 0) g_loss = 0.0;
    }
}

// ---------------------------------------------------------------------------
// K2: per-point A = sum z^2 (sequential chain, identical to R4 sA),
// U = sum |z|, and z -> bf16. grid 1024 x 256, 64 pts/block.
// ---------------------------------------------------------------------------
__global__ void vq_prep_z(const float* __restrict__ z) {
    extern __shared__ float Ze[];          // [k 256][m 64]
    const int t  = threadIdx.x;
    const int tb = blockIdx.x;
    const int b  = tb >> 7;
    const int s0 = (tb & 127) * 64;
    const float* zb = z + (size_t)b * BATCH_STRIDE + s0;

#pragma unroll
    for (int i = 0; i < 16; ++i) {
        int lin = i * 256 + t;
        int k = lin >> 4, mq = lin & 15;
        float4 v = *(const float4*)(zb + (size_t)k * S_DIM + mq * 4);
        *(float4*)(Ze + k * 64 + mq * 4) = v;
        ushort4 u;
        u.x = __bfloat16_as_ushort(__float2bfloat16_rn(v.x));
        u.y = __bfloat16_as_ushort(__float2bfloat16_rn(v.y));
        u.z = __bfloat16_as_ushort(__float2bfloat16_rn(v.z));
        u.w = __bfloat16_as_ushort(__float2bfloat16_rn(v.w));
        *(ushort4*)(g_zbf + (size_t)b * BATCH_STRIDE + (size_t)k * S_DIM + s0 + mq * 4) = u;
    }
    __syncthreads();
    if (t < 64) {
        float a = 0.f, u = 0.f;
#pragma unroll 8
        for (int k = 0; k < 256; ++k) {
            float v = Ze[k * 64 + t];
            a = fmaf(v, v, a);
            u += fabsf(v);
        }
        int p = tb * 64 + t;
        g_A[p] = a;
        g_U[p] = u;
    }
}

// ---------------------------------------------------------------------------
// K3: bf16 tensor-core scoring GEMM, per-lane top-2 candidate slots.
// grid (8 code-tiles, 512 pt-tiles), 256 threads (8 warps).
// Block tile 128 pts x 128 codes x 256 k. Warp tile 32m x 64n.
// ---------------------------------------------------------------------------
__global__ void __launch_bounds__(256)
vq_gemm(const float* __restrict__ unused) {
    extern __shared__ unsigned short smu[];
    unsigned short* Zt = smu;                      // [k][m] : [256][136]
    unsigned short* Et = smu + 256 * ZT_STRIDE;    // [n][k] : [128][264]

    const int t    = threadIdx.x;
    const int lane = t & 31;
    const int warp = t >> 5;
    const int wm   = warp >> 1;          // 0..3
    const int wn   = warp & 1;           // 0..1
    const int ct   = blockIdx.x;         // code tile 0..7
    const int pt_t = blockIdx.y;         // point tile 0..511
    const int b    = pt_t >> 6;
    const int s0   = (pt_t & 63) * 128;

    // Load Z tile (bf16): [k][m], 16B per thread-chunk
    const unsigned short* gz = g_zbf + (size_t)b * BATCH_STRIDE + s0;
#pragma unroll
    for (int i = 0; i < 16; ++i) {
        int lin = i * 256 + t;
        int k = lin >> 4, m8 = lin & 15;
        *(uint4*)(Zt + k * ZT_STRIDE + m8 * 8) = *(const uint4*)(gz + (size_t)k * S_DIM + m8 * 8);
    }
    // Load E tile (bf16): [n][k]
#pragma unroll
    for (int i = 0; i < 16; ++i) {
        int lin = i * 256 + t;
        int n = lin >> 5, kc = lin & 31;
        *(uint4*)(Et + n * ET_STRIDE + kc * 8) =
            *(const uint4*)(g_ebf + (size_t)(ct * 128 + n) * C_DIM + kc * 8);
    }
    __syncthreads();

    float acc[2][8][4];
#pragma unroll
    for (int mf = 0; mf < 2; ++mf)
#pragma unroll
        for (int nt = 0; nt < 8; ++nt)
#pragma unroll
            for (int r = 0; r < 4; ++r) acc[mf][nt][r] = 0.f;

    const unsigned zbase = (unsigned)__cvta_generic_to_shared(Zt);
    const unsigned ebase = (unsigned)__cvta_generic_to_shared(Et);
    const int l7  = lane & 7;
    const int kq8 = ((lane >> 4) & 1) * 8;
    const int mq8 = ((lane >> 3) & 1) * 8;
    const int m0  = wm * 32;
    const int nb  = wn * 64;

    for (int ks = 0; ks < 16; ++ks) {
        const int k0 = ks * 16;
        unsigned a[2][4];
#pragma unroll
        for (int mf = 0; mf < 2; ++mf) {
            // trans ldmatrix from [k][m]: tiles (m0..7,k0..7),(m8..15,k0..7),(m0..7,k8..15),(m8..15,k8..15)
            unsigned addr = zbase +
                (unsigned)(((k0 + l7 + kq8) * ZT_STRIDE + (m0 + mf * 16 + mq8)) * 2);
            ldsm4t(addr, a[mf][0], a[mf][1], a[mf][2], a[mf][3]);
        }
        unsigned bf[8][2];
#pragma unroll
        for (int np = 0; np < 4; ++np) {
            // non-trans from [n][k]: tiles (n0..7,k0..7),(n0..7,k8..15),(n8..15,k0..7),(n8..15,k8..15)
            unsigned addr = ebase +
                (unsigned)(((nb + np * 16 + l7 + kq8) * ET_STRIDE + (k0 + mq8)) * 2);
            unsigned r0, r1, r2, r3;
            ldsm4(addr, r0, r1, r2, r3);
            bf[np * 2][0] = r0; bf[np * 2][1] = r1;
            bf[np * 2 + 1][0] = r2; bf[np * 2 + 1][1] = r3;
        }
#pragma unroll
        for (int mf = 0; mf < 2; ++mf)
#pragma unroll
            for (int nt = 0; nt < 8; ++nt)
                mma_bf16(acc[mf][nt], a[mf], bf[nt]);
    }

    // Epilogue: per-lane top-2 over its 16 codes, per owned point.
    // Lane owns codes j = jbase + nt*8 + c  (nt 0..7, c 0..1).
    const int jbase = ct * 128 + nb + 2 * (lane & 3);
    float Bv[16];
#pragma unroll
    for (int nt = 0; nt < 8; ++nt) {
        Bv[nt * 2]     = g_e2[jbase + nt * 8];
        Bv[nt * 2 + 1] = g_e2[jbase + nt * 8 + 1];
    }
    const int seg = ct * 2 + wn;                 // 0..15
#pragma unroll
    for (int mf = 0; mf < 2; ++mf) {
#pragma unroll
        for (int rh = 0; rh < 2; ++rh) {
            int pt = pt_t * 128 + m0 + mf * 16 + rh * 8 + (lane >> 2);
            float v1 = INFINITY, v2 = INFINITY;
            int j1 = -1, j2 = -1;
#pragma unroll
            for (int nt = 0; nt < 8; ++nt) {
#pragma unroll
                for (int c = 0; c < 2; ++c) {
                    float M = acc[mf][nt][rh * 2 + c];
                    float v = fmaf(-2.f, M, Bv[nt * 2 + c]);
                    int j = jbase + nt * 8 + c;
                    if (v < v1)      { v2 = v1; j2 = j1; v1 = v; j1 = j; }
                    else if (v < v2) { v2 = v;  j2 = j; }
                }
            }
            int base = pt * 128 + seg * 8 + (lane & 3) * 2;
            g_slots[base]     = make_int2(__float_as_int(v1), j1);
            g_slots[base + 1] = make_int2(__float_as_int(v2), j2);
        }
    }
}

// ---------------------------------------------------------------------------
// K4: merge candidates + exact (reference-identical) recheck -> g_idx, idx out.
// grid 1024 x 256, 64 pts/block. Exact chain replicates R4 bit-for-bit.
// ---------------------------------------------------------------------------
__global__ void vq_exact(const float* __restrict__ z,
                         const float* __restrict__ embed,
                         float* __restrict__ out) {
    extern __shared__ float Ze[];          // [k 256][m 64]
    const int t  = threadIdx.x;
    const int tb = blockIdx.x;
    const int b  = tb >> 7;
    const int s0 = (tb & 127) * 64;
    const float* zb = z + (size_t)b * BATCH_STRIDE + s0;

#pragma unroll
    for (int i = 0; i < 16; ++i) {
        int lin = i * 256 + t;
        int k = lin >> 4, mq = lin & 15;
        *(float4*)(Ze + k * 64 + mq * 4) = *(const float4*)(zb + (size_t)k * S_DIM + mq * 4);
    }
    __syncthreads();

    if (t < 64) {
        const int p = tb * 64 + t;
        const float A = g_A[p];
        const float U = g_U[p];
        const int2* sl = g_slots + (size_t)p * 128;

        // pass 1: global approximate min (slot1 = lane min, so gmin = min_j v(j))
        float gmin = INFINITY;
        for (int i = 0; i < 128; ++i) {
            float v = __int_as_float(__ldg((const int*)&sl[i].x));
            gmin = fminf(gmin, v);
        }
        // sound threshold: tau >= gmin + 2*eps, eps <= 2*U*2^-18 = U*7.6e-6.
        const float tau = gmin + fmaf(U, 1.6e-5f, 3.0e-4f);

        float bd = INFINITY; int bi = 1 << 30;
        for (int sp = 0; sp < 64; ++sp) {
            int2 s1 = __ldg((const int2*)&sl[2 * sp]);
            int2 s2 = __ldg((const int2*)&sl[2 * sp + 1]);
            float v2 = __int_as_float(s2.x);
            if (v2 <= tau) {
                // lane-fallback: exact-eval all 16 codes of this lane-pair
                int segb = (sp >> 3) * 128 + ((sp >> 2) & 1) * 64;
                int lp = sp & 3;
#pragma unroll 1
                for (int nt = 0; nt < 8; ++nt) {
                    for (int c = 0; c < 2; ++c) {
                        int j = segb + nt * 8 + 2 * lp + c;
                        float m = 0.f;
                        const float* er = embed + (size_t)j * C_DIM;
#pragma unroll 8
                        for (int k = 0; k < 256; ++k)
                            m = fmaf(Ze[k * 64 + t], __ldg(er + k), m);
                        float d = __fadd_rn(__fadd_rn(A, g_e2[j]), -2.0f * m);
                        if (d < bd || (d == bd && j < bi)) { bd = d; bi = j; }
                    }
                }
            } else if (__int_as_float(s1.x) <= tau) {
                int j = s1.y;
                float m = 0.f;
                const float* er = embed + (size_t)j * C_DIM;
#pragma unroll 8
                for (int k = 0; k < 256; ++k)
                    m = fmaf(Ze[k * 64 + t], __ldg(er + k), m);
                float d = __fadd_rn(__fadd_rn(A, g_e2[j]), -2.0f * m);
                if (d < bd || (d == bd && j < bi)) { bd = d; bi = j; }
            }
        }
        g_idx[p] = bi;
        out[IDX_OFF + p] = (float)bi;
    }
}

// ---------------------------------------------------------------------------
// K5: z_q = fl(z + fl(e - z)), commitment loss, histogram. (unchanged R4)
// ---------------------------------------------------------------------------
__global__ void vq_quantize_kernel(const float* __restrict__ z,
                                   const float* __restrict__ embed,
                                   float* __restrict__ out) {
    __shared__ int    sidx[64];
    __shared__ double red[256];

    const int t  = threadIdx.x;
    const int tb = blockIdx.x;
    const int b  = tb >> 7;
    const int s0 = (tb & 127) * 64;

    if (t < 64) {
        int id = g_idx[tb * 64 + t];
        sidx[t] = id;
        atomicAdd(&g_cnt[id], 1.0f);
    }
    __syncthreads();

    const float* zb = z   + (size_t)b * BATCH_STRIDE + s0;
    float*       qb = out + ZQ_OFF + (size_t)b * BATCH_STRIDE + s0;

    double lacc = 0.0;
#pragma unroll
    for (int i = 0; i < 16; ++i) {
        int lin = i * 256 + t;
        int c = lin >> 4, mq = lin & 15;
        float4 zv = *(const float4*)(zb + (size_t)c * S_DIM + mq * 4);
        float4 ev;
        ev.x = __ldg(embed + (size_t)sidx[mq * 4 + 0] * C_DIM + c);
        ev.y = __ldg(embed + (size_t)sidx[mq * 4 + 1] * C_DIM + c);
        ev.z = __ldg(embed + (size_t)sidx[mq * 4 + 2] * C_DIM + c);
        ev.w = __ldg(embed + (size_t)sidx[mq * 4 + 3] * C_DIM + c);
        float dx = __fadd_rn(ev.x, -zv.x);
        float dy = __fadd_rn(ev.y, -zv.y);
        float dz = __fadd_rn(ev.z, -zv.z);
        float dw = __fadd_rn(ev.w, -zv.w);
        float4 qv;
        qv.x = __fadd_rn(zv.x, dx);
        qv.y = __fadd_rn(zv.y, dy);
        qv.z = __fadd_rn(zv.z, dz);
        qv.w = __fadd_rn(zv.w, dw);
        *(float4*)(qb + (size_t)c * S_DIM + mq * 4) = qv;
        lacc += (double)(dx * dx) + (double)(dy * dy)
              + (double)(dz * dz) + (double)(dw * dw);
    }

    red[t] = lacc;
    __syncthreads();
    for (int off = 128; off > 0; off >>= 1) {
        if (t < off) red[t] += red[t + off];
        __syncthreads();
    }
    if (t == 0) atomicAdd(&g_loss, red[0]);
}

// ---------------------------------------------------------------------------
// K6: finalize loss + perplexity.
// ---------------------------------------------------------------------------
__global__ void vq_finalize_kernel(float* __restrict__ out) {
    __shared__ float sred[1024];
    int t = threadIdx.x;
    float p = g_cnt[t] * (1.0f / (float)N_PTS);
    sred[t] = p * logf(p + 1e-10f);
    __syncthreads();
    for (int off = 512; off > 0; off >>= 1) {
        if (t < off) sred[t] += sred[t + off];
        __syncthreads();
    }
    if (t == 0) {
        out[PERP_OFF] = expf(-sred[0]);
        out[LOSS_OFF] = 0.25f * (float)(g_loss / (double)Z_ELEMS);
    }
}

// ---------------------------------------------------------------------------
extern "C" void kernel_launch(void* const* d_in, const int* in_sizes, int n_in,
                              void* d_out, int out_size) {
    const float* z     = (const float*)d_in[0];
    const float* embed = (const float*)d_in[1];
    float* out = (float*)d_out;

    cudaFuncSetAttribute(vq_gemm,  cudaFuncAttributeMaxDynamicSharedMemorySize, SMEM_GEMM);
    cudaFuncSetAttribute(vq_prep_z, cudaFuncAttributeMaxDynamicSharedMemorySize, SMEM_TILE64);
    cudaFuncSetAttribute(vq_exact,  cudaFuncAttributeMaxDynamicSharedMemorySize, SMEM_TILE64);

    vq_prep_e<<<128, 256>>>(embed);
    vq_prep_z<<<1024, 256, SMEM_TILE64>>>(z);
    vq_gemm<<<dim3(8, 512), 256, SMEM_GEMM>>>(z);
    vq_exact<<<1024, 256, SMEM_TILE64>>>(z, embed, out);
    vq_quantize_kernel<<<1024, 256>>>(z, embed, out);
    vq_finalize_kernel<<<1, 1024>>>(out);
}

// round 7
// speedup vs baseline: 1.0005x; 1.0005x over previous
#include <cuda_runtime.h>
#include <cuda_bf16.h>
#include <cstdint>
#include <math.h>

// Problem constants
#define B_DIM 8
#define C_DIM 256
#define S_DIM 8192            // D*H*W
#define N_PTS 65536           // B*S
#define N_CODES 1024
#define Z_ELEMS 16777216
#define BATCH_STRIDE 2097152  // C*S

// Output layout (concatenated, fp32)
#define ZQ_OFF 0
#define IDX_OFF 16777216
#define LOSS_OFF 16842752
#define PERP_OFF 16842753

// Phase-1 GEMM tiling: block = 128 pts x 128 codes x 256 k (all-K resident)
#define ZT_STRIDE 136         // 128 m + 8 pad (bf16)
#define ET_STRIDE 264         // 256 k + 8 pad (bf16)
#define SMEM_GEMM (256*ZT_STRIDE*2 + 128*ET_STRIDE*2)   // 137216 B
#define SMEM_TILE64 (256*64*4)                           // 65536 B

// Scratch (device globals)
__device__ float          g_e2[N_CODES];          // ||e_j||^2 (R4 shuffle chain)
__device__ float          g_A[N_PTS];             // sum z^2 (sequential chain)
__device__ float          g_U[N_PTS];             // sum |z| (for error bound)
__device__ int            g_idx[N_PTS];
__device__ float          g_cnt[N_CODES];
__device__ double         g_loss;
__device__ unsigned short g_zbf[Z_ELEMS];         // z as bf16, same [b][k][s] layout
__device__ unsigned short g_ebf[N_CODES * C_DIM]; // embed as bf16 [code][k]
__device__ int2           g_slots[N_PTS * 128];   // per (pt,seg,lanepair): top-2 {v_bits, j}

// ---- PTX helpers -----------------------------------------------------------
__device__ __forceinline__ void ldsm4(unsigned a, unsigned& r0, unsigned& r1,
                                      unsigned& r2, unsigned& r3) {
    asm volatile("ldmatrix.sync.aligned.m8n8.x4.shared.b16 {%0,%1,%2,%3}, [%4];"
                 : "=r"(r0), "=r"(r1), "=r"(r2), "=r"(r3) : "r"(a));
}
__device__ __forceinline__ void ldsm4t(unsigned a, unsigned& r0, unsigned& r1,
                                       unsigned& r2, unsigned& r3) {
    asm volatile("ldmatrix.sync.aligned.m8n8.x4.trans.shared.b16 {%0,%1,%2,%3}, [%4];"
                 : "=r"(r0), "=r"(r1), "=r"(r2), "=r"(r3) : "r"(a));
}
__device__ __forceinline__ void mma_bf16(float* d, const unsigned* a, const unsigned* b) {
    asm volatile(
        "mma.sync.aligned.m16n8k16.row.col.f32.bf16.bf16.f32 "
        "{%0,%1,%2,%3}, {%4,%5,%6,%7}, {%8,%9}, {%0,%1,%2,%3};"
        : "+f"(d[0]), "+f"(d[1]), "+f"(d[2]), "+f"(d[3])
        : "r"(a[0]), "r"(a[1]), "r"(a[2]), "r"(a[3]), "r"(b[0]), "r"(b[1]));
}

// ---------------------------------------------------------------------------
// K1: ||e_j||^2 (unchanged R4 chain), embed->bf16, zero accumulators.
// grid 128 x 256.
// ---------------------------------------------------------------------------
__global__ void vq_prep_e(const float* __restrict__ embed) {
    int t = threadIdx.x, lane = t & 31;
    int code = blockIdx.x * 8 + (t >> 5);
    const float* row = embed + code * C_DIM;
    float s = 0.f;
#pragma unroll
    for (int q = 0; q < 8; ++q) { float e = row[lane + q * 32]; s = fmaf(e, e, s); }
#pragma unroll
    for (int off = 16; off > 0; off >>= 1) s += __shfl_down_sync(0xffffffffu, s, off);
    if (lane == 0) g_e2[code] = s;

    // bf16 copy of embed: this block handles 8 codes = 2048 elems
#pragma unroll
    for (int i = 0; i < 8; ++i) {
        int gi = blockIdx.x * 2048 + i * 256 + t;
        g_ebf[gi] = __bfloat16_as_ushort(__float2bfloat16_rn(embed[gi]));
    }
    if (blockIdx.x == 0) {
        for (int i = t; i < N_CODES; i += 256) g_cnt[i] = 0.f;
        if (t == 0) g_loss = 0.0;
    }
}

// ---------------------------------------------------------------------------
// K2: per-point A = sum z^2 (sequential chain, identical to R4 sA),
// U = sum |z|, and z -> bf16. grid 1024 x 256, 64 pts/block.
// ---------------------------------------------------------------------------
__global__ void vq_prep_z(const float* __restrict__ z) {
    extern __shared__ float Ze[];          // [k 256][m 64]
    const int t  = threadIdx.x;
    const int tb = blockIdx.x;
    const int b  = tb >> 7;
    const int s0 = (tb & 127) * 64;
    const float* zb = z + (size_t)b * BATCH_STRIDE + s0;

#pragma unroll
    for (int i = 0; i < 16; ++i) {
        int lin = i * 256 + t;
        int k = lin >> 4, mq = lin & 15;
        float4 v = *(const float4*)(zb + (size_t)k * S_DIM + mq * 4);
        *(float4*)(Ze + k * 64 + mq * 4) = v;
        ushort4 u;
        u.x = __bfloat16_as_ushort(__float2bfloat16_rn(v.x));
        u.y = __bfloat16_as_ushort(__float2bfloat16_rn(v.y));
        u.z = __bfloat16_as_ushort(__float2bfloat16_rn(v.z));
        u.w = __bfloat16_as_ushort(__float2bfloat16_rn(v.w));
        *(ushort4*)(g_zbf + (size_t)b * BATCH_STRIDE + (size_t)k * S_DIM + s0 + mq * 4) = u;
    }
    __syncthreads();
    if (t < 64) {
        float a = 0.f, u = 0.f;
#pragma unroll 8
        for (int k = 0; k < 256; ++k) {
            float v = Ze[k * 64 + t];
            a = fmaf(v, v, a);
            u += fabsf(v);
        }
        int p = tb * 64 + t;
        g_A[p] = a;
        g_U[p] = u;
    }
}

// ---------------------------------------------------------------------------
// K3: bf16 tensor-core scoring GEMM, per-lane top-2 candidate slots.
// grid (8 code-tiles, 512 pt-tiles), 256 threads (8 warps).
// Block tile 128 pts x 128 codes x 256 k. Warp tile 32m x 64n.
// ---------------------------------------------------------------------------
__global__ void __launch_bounds__(256)
vq_gemm(const float* __restrict__ unused) {
    extern __shared__ unsigned short smu[];
    unsigned short* Zt = smu;                      // [k][m] : [256][136]
    unsigned short* Et = smu + 256 * ZT_STRIDE;    // [n][k] : [128][264]

    const int t    = threadIdx.x;
    const int lane = t & 31;
    const int warp = t >> 5;
    const int wm   = warp >> 1;          // 0..3
    const int wn   = warp & 1;           // 0..1
    const int ct   = blockIdx.x;         // code tile 0..7
    const int pt_t = blockIdx.y;         // point tile 0..511
    const int b    = pt_t >> 6;
    const int s0   = (pt_t & 63) * 128;

    // Load Z tile (bf16): [k][m], 16B per thread-chunk
    const unsigned short* gz = g_zbf + (size_t)b * BATCH_STRIDE + s0;
#pragma unroll
    for (int i = 0; i < 16; ++i) {
        int lin = i * 256 + t;
        int k = lin >> 4, m8 = lin & 15;
        *(uint4*)(Zt + k * ZT_STRIDE + m8 * 8) = *(const uint4*)(gz + (size_t)k * S_DIM + m8 * 8);
    }
    // Load E tile (bf16): [n][k]
#pragma unroll
    for (int i = 0; i < 16; ++i) {
        int lin = i * 256 + t;
        int n = lin >> 5, kc = lin & 31;
        *(uint4*)(Et + n * ET_STRIDE + kc * 8) =
            *(const uint4*)(g_ebf + (size_t)(ct * 128 + n) * C_DIM + kc * 8);
    }
    __syncthreads();

    float acc[2][8][4];
#pragma unroll
    for (int mf = 0; mf < 2; ++mf)
#pragma unroll
        for (int nt = 0; nt < 8; ++nt)
#pragma unroll
            for (int r = 0; r < 4; ++r) acc[mf][nt][r] = 0.f;

    const unsigned zbase = (unsigned)__cvta_generic_to_shared(Zt);
    const unsigned ebase = (unsigned)__cvta_generic_to_shared(Et);
    const int l7  = lane & 7;
    const int kq8 = ((lane >> 4) & 1) * 8;
    const int mq8 = ((lane >> 3) & 1) * 8;
    const int m0  = wm * 32;
    const int nb  = wn * 64;

    for (int ks = 0; ks < 16; ++ks) {
        const int k0 = ks * 16;
        unsigned a[2][4];
#pragma unroll
        for (int mf = 0; mf < 2; ++mf) {
            // trans ldmatrix from [k][m]: tiles (m0..7,k0..7),(m8..15,k0..7),(m0..7,k8..15),(m8..15,k8..15)
            unsigned addr = zbase +
                (unsigned)(((k0 + l7 + kq8) * ZT_STRIDE + (m0 + mf * 16 + mq8)) * 2);
            ldsm4t(addr, a[mf][0], a[mf][1], a[mf][2], a[mf][3]);
        }
        unsigned bf[8][2];
#pragma unroll
        for (int np = 0; np < 4; ++np) {
            // non-trans from [n][k]: tiles (n0..7,k0..7),(n0..7,k8..15),(n8..15,k0..7),(n8..15,k8..15)
            unsigned addr = ebase +
                (unsigned)(((nb + np * 16 + l7 + kq8) * ET_STRIDE + (k0 + mq8)) * 2);
            unsigned r0, r1, r2, r3;
            ldsm4(addr, r0, r1, r2, r3);
            bf[np * 2][0] = r0; bf[np * 2][1] = r1;
            bf[np * 2 + 1][0] = r2; bf[np * 2 + 1][1] = r3;
        }
#pragma unroll
        for (int mf = 0; mf < 2; ++mf)
#pragma unroll
            for (int nt = 0; nt < 8; ++nt)
                mma_bf16(acc[mf][nt], a[mf], bf[nt]);
    }

    // Epilogue: per-lane top-2 over its 16 codes, per owned point.
    // Lane owns codes j = jbase + nt*8 + c  (nt 0..7, c 0..1).
    const int jbase = ct * 128 + nb + 2 * (lane & 3);
    float Bv[16];
#pragma unroll
    for (int nt = 0; nt < 8; ++nt) {
        Bv[nt * 2]     = g_e2[jbase + nt * 8];
        Bv[nt * 2 + 1] = g_e2[jbase + nt * 8 + 1];
    }
    const int seg = ct * 2 + wn;                 // 0..15
#pragma unroll
    for (int mf = 0; mf < 2; ++mf) {
#pragma unroll
        for (int rh = 0; rh < 2; ++rh) {
            int pt = pt_t * 128 + m0 + mf * 16 + rh * 8 + (lane >> 2);
            float v1 = INFINITY, v2 = INFINITY;
            int j1 = -1, j2 = -1;
#pragma unroll
            for (int nt = 0; nt < 8; ++nt) {
#pragma unroll
                for (int c = 0; c < 2; ++c) {
                    float M = acc[mf][nt][rh * 2 + c];
                    float v = fmaf(-2.f, M, Bv[nt * 2 + c]);
                    int j = jbase + nt * 8 + c;
                    if (v < v1)      { v2 = v1; j2 = j1; v1 = v; j1 = j; }
                    else if (v < v2) { v2 = v;  j2 = j; }
                }
            }
            int base = pt * 128 + seg * 8 + (lane & 3) * 2;
            g_slots[base]     = make_int2(__float_as_int(v1), j1);
            g_slots[base + 1] = make_int2(__float_as_int(v2), j2);
        }
    }
}

// ---------------------------------------------------------------------------
// K4: merge candidates + exact (reference-identical) recheck -> g_idx, idx out.
// grid 1024 x 256, 64 pts/block. Exact chain replicates R4 bit-for-bit.
// ---------------------------------------------------------------------------
__global__ void vq_exact(const float* __restrict__ z,
                         const float* __restrict__ embed,
                         float* __restrict__ out) {
    extern __shared__ float Ze[];          // [k 256][m 64]
    const int t  = threadIdx.x;
    const int tb = blockIdx.x;
    const int b  = tb >> 7;
    const int s0 = (tb & 127) * 64;
    const float* zb = z + (size_t)b * BATCH_STRIDE + s0;

#pragma unroll
    for (int i = 0; i < 16; ++i) {
        int lin = i * 256 + t;
        int k = lin >> 4, mq = lin & 15;
        *(float4*)(Ze + k * 64 + mq * 4) = *(const float4*)(zb + (size_t)k * S_DIM + mq * 4);
    }
    __syncthreads();

    if (t < 64) {
        const int p = tb * 64 + t;
        const float A = g_A[p];
        const float U = g_U[p];
        const int2* sl = g_slots + (size_t)p * 128;

        // pass 1: global approximate min (slot1 = lane min, so gmin = min_j v(j))
        float gmin = INFINITY;
        for (int i = 0; i < 128; ++i) {
            float v = __int_as_float(__ldg((const int*)&sl[i].x));
            gmin = fminf(gmin, v);
        }
        // sound threshold: tau >= gmin + 2*eps, eps <= 2*U*2^-18 = U*7.6e-6.
        const float tau = gmin + fmaf(U, 1.6e-5f, 3.0e-4f);

        float bd = INFINITY; int bi = 1 << 30;
        for (int sp = 0; sp < 64; ++sp) {
            int2 s1 = __ldg((const int2*)&sl[2 * sp]);
            int2 s2 = __ldg((const int2*)&sl[2 * sp + 1]);
            float v2 = __int_as_float(s2.x);
            if (v2 <= tau) {
                // lane-fallback: exact-eval all 16 codes of this lane-pair
                int segb = (sp >> 3) * 128 + ((sp >> 2) & 1) * 64;
                int lp = sp & 3;
#pragma unroll 1
                for (int nt = 0; nt < 8; ++nt) {
                    for (int c = 0; c < 2; ++c) {
                        int j = segb + nt * 8 + 2 * lp + c;
                        float m = 0.f;
                        const float* er = embed + (size_t)j * C_DIM;
#pragma unroll 8
                        for (int k = 0; k < 256; ++k)
                            m = fmaf(Ze[k * 64 + t], __ldg(er + k), m);
                        float d = __fadd_rn(__fadd_rn(A, g_e2[j]), -2.0f * m);
                        if (d < bd || (d == bd && j < bi)) { bd = d; bi = j; }
                    }
                }
            } else if (__int_as_float(s1.x) <= tau) {
                int j = s1.y;
                float m = 0.f;
                const float* er = embed + (size_t)j * C_DIM;
#pragma unroll 8
                for (int k = 0; k < 256; ++k)
                    m = fmaf(Ze[k * 64 + t], __ldg(er + k), m);
                float d = __fadd_rn(__fadd_rn(A, g_e2[j]), -2.0f * m);
                if (d < bd || (d == bd && j < bi)) { bd = d; bi = j; }
            }
        }
        g_idx[p] = bi;
        out[IDX_OFF + p] = (float)bi;
    }
}

// ---------------------------------------------------------------------------
// K5: z_q = fl(z + fl(e - z)), commitment loss, histogram. (unchanged R4)
// ---------------------------------------------------------------------------
__global__ void vq_quantize_kernel(const float* __restrict__ z,
                                   const float* __restrict__ embed,
                                   float* __restrict__ out) {
    __shared__ int    sidx[64];
    __shared__ double red[256];

    const int t  = threadIdx.x;
    const int tb = blockIdx.x;
    const int b  = tb >> 7;
    const int s0 = (tb & 127) * 64;

    if (t < 64) {
        int id = g_idx[tb * 64 + t];
        sidx[t] = id;
        atomicAdd(&g_cnt[id], 1.0f);
    }
    __syncthreads();

    const float* zb = z   + (size_t)b * BATCH_STRIDE + s0;
    float*       qb = out + ZQ_OFF + (size_t)b * BATCH_STRIDE + s0;

    double lacc = 0.0;
#pragma unroll
    for (int i = 0; i < 16; ++i) {
        int lin = i * 256 + t;
        int c = lin >> 4, mq = lin & 15;
        float4 zv = *(const float4*)(zb + (size_t)c * S_DIM + mq * 4);
        float4 ev;
        ev.x = __ldg(embed + (size_t)sidx[mq * 4 + 0] * C_DIM + c);
        ev.y = __ldg(embed + (size_t)sidx[mq * 4 + 1] * C_DIM + c);
        ev.z = __ldg(embed + (size_t)sidx[mq * 4 + 2] * C_DIM + c);
        ev.w = __ldg(embed + (size_t)sidx[mq * 4 + 3] * C_DIM + c);
        float dx = __fadd_rn(ev.x, -zv.x);
        float dy = __fadd_rn(ev.y, -zv.y);
        float dz = __fadd_rn(ev.z, -zv.z);
        float dw = __fadd_rn(ev.w, -zv.w);
        float4 qv;
        qv.x = __fadd_rn(zv.x, dx);
        qv.y = __fadd_rn(zv.y, dy);
        qv.z = __fadd_rn(zv.z, dz);
        qv.w = __fadd_rn(zv.w, dw);
        *(float4*)(qb + (size_t)c * S_DIM + mq * 4) = qv;
        lacc += (double)(dx * dx) + (double)(dy * dy)
              + (double)(dz * dz) + (double)(dw * dw);
    }

    red[t] = lacc;
    __syncthreads();
    for (int off = 128; off > 0; off >>= 1) {
        if (t < off) red[t] += red[t + off];
        __syncthreads();
    }
    if (t == 0) atomicAdd(&g_loss, red[0]);
}

// ---------------------------------------------------------------------------
// K6: finalize loss + perplexity.
// ---------------------------------------------------------------------------
__global__ void vq_finalize_kernel(float* __restrict__ out) {
    __shared__ float sred[1024];
    int t = threadIdx.x;
    float p = g_cnt[t] * (1.0f / (float)N_PTS);
    sred[t] = p * logf(p + 1e-10f);
    __syncthreads();
    for (int off = 512; off > 0; off >>= 1) {
        if (t < off) sred[t] += sred[t + off];
        __syncthreads();
    }
    if (t == 0) {
        out[PERP_OFF] = expf(-sred[0]);
        out[LOSS_OFF] = 0.25f * (float)(g_loss / (double)Z_ELEMS);
    }
}

// ---------------------------------------------------------------------------
extern "C" void kernel_launch(void* const* d_in, const int* in_sizes, int n_in,
                              void* d_out, int out_size) {
    const float* z     = (const float*)d_in[0];
    const float* embed = (const float*)d_in[1];
    float* out = (float*)d_out;

    cudaFuncSetAttribute(vq_gemm,  cudaFuncAttributeMaxDynamicSharedMemorySize, SMEM_GEMM);
    cudaFuncSetAttribute(vq_prep_z, cudaFuncAttributeMaxDynamicSharedMemorySize, SMEM_TILE64);
    cudaFuncSetAttribute(vq_exact,  cudaFuncAttributeMaxDynamicSharedMemorySize, SMEM_TILE64);

    vq_prep_e<<<128, 256>>>(embed);
    vq_prep_z<<<1024, 256, SMEM_TILE64>>>(z);
    vq_gemm<<<dim3(8, 512), 256, SMEM_GEMM>>>(z);
    vq_exact<<<1024, 256, SMEM_TILE64>>>(z, embed, out);
    vq_quantize_kernel<<<1024, 256>>>(z, embed, out);
    vq_finalize_kernel<<<1, 1024>>>(out);
}